// round 1
// baseline (speedup 1.0000x reference)
#include <cuda_runtime.h>
#include <cuda_bf16.h>
#include <math.h>

#define N_NODES 100000
#define N_EDGES 1200000
#define CH 64

// ---------------- scratch (static device memory; no allocs allowed) ----------
__device__ float g_xin [N_NODES * CH];
__device__ float g_mean[N_NODES * CH];
__device__ float g_h1  [N_NODES * CH];
__device__ float g_h2  [N_NODES * CH];
__device__ int   g_deg [N_NODES];
__device__ int   g_rowstart[N_NODES + 1];
__device__ int   g_fill[N_NODES];
__device__ int   g_src_sorted[N_EDGES];
__device__ int   g_is64;

// ---------------- edge-index dtype detection (int64 vs int32) ----------------
__global__ void detect_kernel(const void* ei) {
    // If int64 little-endian with values < 2^31, every odd 32-bit word is 0.
    const int* w = (const int*)ei;
    int ok64 = 1;
    for (int i = 0; i < 64; ++i)
        if (w[2 * i + 1] != 0) ok64 = 0;
    g_is64 = ok64;
}

__device__ __forceinline__ int load_idx(const void* ei, long long pos) {
    if (g_is64) return (int)((const long long*)ei)[pos];
    return ((const int*)ei)[pos];
}

// ---------------- prep: nan_to_num(x) -> xin, zero degrees -------------------
__global__ void prep_kernel(const float* __restrict__ x) {
    int i = blockIdx.x * blockDim.x + threadIdx.x;
    if (i < N_NODES * CH) {
        float v = x[i];
        g_xin[i] = isnan(v) ? 0.0f : v;
    }
    if (i < N_NODES) g_deg[i] = 0;
}

// ---------------- count degrees ----------------------------------------------
__global__ void count_kernel(const void* __restrict__ ei) {
    int e = blockIdx.x * blockDim.x + threadIdx.x;
    if (e < N_EDGES) {
        int d = load_idx(ei, (long long)N_EDGES + e);
        atomicAdd(&g_deg[d], 1);
    }
}

// ---------------- single-block exclusive scan --------------------------------
__global__ void scan_kernel() {
    __shared__ int warp_sums[32];
    __shared__ int s_carry;
    int tid = threadIdx.x;
    int lane = tid & 31, w = tid >> 5;
    if (tid == 0) { s_carry = 0; g_rowstart[0] = 0; }
    __syncthreads();
    for (int base = 0; base < N_NODES; base += 1024) {
        int i = base + tid;
        int v = (i < N_NODES) ? g_deg[i] : 0;
        int incl = v;
        #pragma unroll
        for (int d = 1; d < 32; d <<= 1) {
            int t = __shfl_up_sync(0xffffffffu, incl, d);
            if (lane >= d) incl += t;
        }
        if (lane == 31) warp_sums[w] = incl;
        __syncthreads();
        if (w == 0) {
            int ws = warp_sums[lane];
            #pragma unroll
            for (int d = 1; d < 32; d <<= 1) {
                int t = __shfl_up_sync(0xffffffffu, ws, d);
                if (lane >= d) ws += t;
            }
            warp_sums[lane] = ws;  // inclusive scan of warp totals
        }
        __syncthreads();
        int offset = s_carry + (w > 0 ? warp_sums[w - 1] : 0);
        int inclusive = offset + incl;
        if (i < N_NODES) {
            g_rowstart[i + 1] = inclusive;
            g_fill[i] = inclusive - v;   // exclusive position for fill phase
        }
        __syncthreads();
        if (tid == 1023) s_carry = inclusive;
        __syncthreads();
    }
}

// ---------------- fill CSR (counting sort of src by dst) ---------------------
__global__ void fill_kernel(const void* __restrict__ ei) {
    int e = blockIdx.x * blockDim.x + threadIdx.x;
    if (e < N_EDGES) {
        int s = load_idx(ei, e);
        int d = load_idx(ei, (long long)N_EDGES + e);
        int pos = atomicAdd(&g_fill[d], 1);
        g_src_sorted[pos] = s;
    }
}

// ---------------- segment mean: one warp per destination node ----------------
__global__ void __launch_bounds__(256) segmean_kernel(const float* __restrict__ feat,
                                                      float* __restrict__ outm) {
    int warp = (blockIdx.x * blockDim.x + threadIdx.x) >> 5;
    if (warp >= N_NODES) return;
    int lane = threadIdx.x & 31;
    int beg = g_rowstart[warp];
    int end = g_rowstart[warp + 1];
    float a0 = 0.f, a1 = 0.f, b0 = 0.f, b1 = 0.f;
    int i = beg;
    for (; i + 1 < end; i += 2) {
        int s0 = g_src_sorted[i];
        int s1 = g_src_sorted[i + 1];
        const float* p0 = feat + (long long)s0 * CH;
        const float* p1 = feat + (long long)s1 * CH;
        a0 += p0[lane]; a1 += p0[lane + 32];
        b0 += p1[lane]; b1 += p1[lane + 32];
    }
    if (i < end) {
        int s0 = g_src_sorted[i];
        const float* p0 = feat + (long long)s0 * CH;
        a0 += p0[lane]; a1 += p0[lane + 32];
    }
    a0 += b0; a1 += b1;
    int cnt = end - beg;
    float inv = 1.0f / (float)max(cnt, 1);
    outm[(long long)warp * CH + lane]      = a0 * inv;
    outm[(long long)warp * CH + lane + 32] = a1 * inv;
}

// ---------------- dense: out = relu?(mean@Wl + b + root@Wr) ------------------
// 256 threads, 32 nodes/block, each thread handles one out-channel j for 8 nodes.
#define DN 32
__global__ void __launch_bounds__(256) dense_kernel(
    const float* __restrict__ mean, const float* __restrict__ root,
    const float* __restrict__ Wl, const float* __restrict__ Wr,
    const float* __restrict__ bias, float* __restrict__ out, int do_relu) {
    __shared__ float  sWl[64 * 64];
    __shared__ float  sWr[64 * 64];
    __shared__ float4 sM[DN * 16];
    __shared__ float4 sR[DN * 16];
    int tid = threadIdx.x;
    int j = tid & 63, g = tid >> 6;        // g in 0..3
    int nodeBase = blockIdx.x * DN;

    // stage weights (1024 float4 each)
    for (int i = tid; i < 64 * 16; i += 256) {
        ((float4*)sWl)[i] = ((const float4*)Wl)[i];
        ((float4*)sWr)[i] = ((const float4*)Wr)[i];
    }
    // stage node features (DN*16 float4 each)
    for (int i = tid; i < DN * 16; i += 256) {
        int node = nodeBase + (i >> 4);
        int c = i & 15;
        float4 z = make_float4(0.f, 0.f, 0.f, 0.f);
        sM[i] = (node < N_NODES) ? ((const float4*)mean)[(long long)node * 16 + c] : z;
        sR[i] = (node < N_NODES) ? ((const float4*)root)[(long long)node * 16 + c] : z;
    }
    __syncthreads();

    float bj = bias[j];
    float acc[8];
    #pragma unroll
    for (int i = 0; i < 8; ++i) acc[i] = bj;

    #pragma unroll 4
    for (int k4 = 0; k4 < 16; ++k4) {
        float wl0 = sWl[(k4 * 4 + 0) * 64 + j];
        float wl1 = sWl[(k4 * 4 + 1) * 64 + j];
        float wl2 = sWl[(k4 * 4 + 2) * 64 + j];
        float wl3 = sWl[(k4 * 4 + 3) * 64 + j];
        float wr0 = sWr[(k4 * 4 + 0) * 64 + j];
        float wr1 = sWr[(k4 * 4 + 1) * 64 + j];
        float wr2 = sWr[(k4 * 4 + 2) * 64 + j];
        float wr3 = sWr[(k4 * 4 + 3) * 64 + j];
        #pragma unroll
        for (int i = 0; i < 8; ++i) {
            int ln = g * 8 + i;
            float4 m = sM[ln * 16 + k4];
            float4 r = sR[ln * 16 + k4];
            float a = acc[i];
            a = fmaf(m.x, wl0, a); a = fmaf(m.y, wl1, a);
            a = fmaf(m.z, wl2, a); a = fmaf(m.w, wl3, a);
            a = fmaf(r.x, wr0, a); a = fmaf(r.y, wr1, a);
            a = fmaf(r.z, wr2, a); a = fmaf(r.w, wr3, a);
            acc[i] = a;
        }
    }

    #pragma unroll
    for (int i = 0; i < 8; ++i) {
        int node = nodeBase + g * 8 + i;
        if (node < N_NODES) {
            float v = acc[i];
            if (do_relu) v = fmaxf(v, 0.f);
            out[(long long)node * CH + j] = v;
        }
    }
}

// ---------------- fc head: pred[n] = h2[n,:] @ Wfc + bfc ---------------------
__global__ void __launch_bounds__(256) fc_kernel(const float* __restrict__ h,
                                                 const float* __restrict__ Wfc,
                                                 const float* __restrict__ bfc,
                                                 float* __restrict__ out) {
    int warp = (blockIdx.x * blockDim.x + threadIdx.x) >> 5;
    if (warp >= N_NODES) return;
    int lane = threadIdx.x & 31;
    const float* p = h + (long long)warp * CH;
    float v = p[lane] * Wfc[lane] + p[lane + 32] * Wfc[lane + 32];
    #pragma unroll
    for (int d = 16; d; d >>= 1) v += __shfl_xor_sync(0xffffffffu, v, d);
    if (lane == 0) out[warp] = v + bfc[0];
}

// ---------------- launch -----------------------------------------------------
extern "C" void kernel_launch(void* const* d_in, const int* in_sizes, int n_in,
                              void* d_out, int out_size) {
    const float* x   = (const float*)d_in[0];
    const void*  ei  = d_in[1];
    const float* W1l = (const float*)d_in[2];
    const float* b1  = (const float*)d_in[3];
    const float* W1r = (const float*)d_in[4];
    const float* W2l = (const float*)d_in[5];
    const float* b2  = (const float*)d_in[6];
    const float* W2r = (const float*)d_in[7];
    const float* Wfc = (const float*)d_in[8];
    const float* bfc = (const float*)d_in[9];
    float* out = (float*)d_out;

    float *xin, *mean, *h1, *h2;
    cudaGetSymbolAddress((void**)&xin,  g_xin);
    cudaGetSymbolAddress((void**)&mean, g_mean);
    cudaGetSymbolAddress((void**)&h1,   g_h1);
    cudaGetSymbolAddress((void**)&h2,   g_h2);

    const int T = 256;
    int gridPrep  = (N_NODES * CH + T - 1) / T;
    int gridEdge  = (N_EDGES + T - 1) / T;
    int gridWarp  = (N_NODES * 32 + T - 1) / T;   // one warp per node
    int gridDense = (N_NODES + DN - 1) / DN;

    detect_kernel<<<1, 1>>>(ei);
    prep_kernel<<<gridPrep, T>>>(x);
    count_kernel<<<gridEdge, T>>>(ei);
    scan_kernel<<<1, 1024>>>();
    fill_kernel<<<gridEdge, T>>>(ei);

    // layer 1
    segmean_kernel<<<gridWarp, T>>>(xin, mean);
    dense_kernel<<<gridDense, T>>>(mean, xin, W1l, W1r, b1, h1, 1);
    // layer 2
    segmean_kernel<<<gridWarp, T>>>(h1, mean);
    dense_kernel<<<gridDense, T>>>(mean, h1, W2l, W2r, b2, h2, 1);
    // head
    fc_kernel<<<gridWarp, T>>>(h2, Wfc, bfc, out);
}

// round 3
// speedup vs baseline: 1.8025x; 1.8025x over previous
#include <cuda_runtime.h>
#include <cuda_bf16.h>
#include <math.h>

#define N_NODES 100000
#define N_EDGES 1200000
#define CH 64
#define SCAN_B 1024
#define NB ((N_NODES + SCAN_B - 1) / SCAN_B)   // 98 blocks

// ---------------- scratch (static device memory; no allocs allowed) ----------
__device__ float g_xin [N_NODES * CH];
__device__ float g_mean[N_NODES * CH];
__device__ float g_h1  [N_NODES * CH];
__device__ float g_h2  [N_NODES * CH];
__device__ int   g_deg [N_NODES];
__device__ int   g_rowstart[N_NODES + 1];
__device__ int   g_fill[N_NODES];
__device__ int   g_src_sorted[N_EDGES];
__device__ int   g_bsum[NB];
__device__ int   g_boff[NB];
__device__ int   g_is64;

// ---------------- edge-index dtype detection (int64 vs int32) ----------------
__global__ void detect_kernel(const void* ei) {
    const int* w = (const int*)ei;
    int ok64 = 1;
    for (int i = 0; i < 64; ++i)
        if (w[2 * i + 1] != 0) ok64 = 0;
    g_is64 = ok64;
}

__device__ __forceinline__ int load_idx(const void* ei, long long pos) {
    if (g_is64) return (int)((const long long*)ei)[pos];
    return ((const int*)ei)[pos];
}

// ---------------- prep: nan_to_num(x) -> xin (float4), zero degrees ----------
__global__ void prep_kernel(const float* __restrict__ x) {
    int i = blockIdx.x * blockDim.x + threadIdx.x;
    if (i < N_NODES * CH / 4) {
        float4 v = ((const float4*)x)[i];
        v.x = isnan(v.x) ? 0.f : v.x;
        v.y = isnan(v.y) ? 0.f : v.y;
        v.z = isnan(v.z) ? 0.f : v.z;
        v.w = isnan(v.w) ? 0.f : v.w;
        ((float4*)g_xin)[i] = v;
    }
    if (i < N_NODES) g_deg[i] = 0;
}

// ---------------- count degrees ----------------------------------------------
__global__ void count_kernel(const void* __restrict__ ei) {
    int e = blockIdx.x * blockDim.x + threadIdx.x;
    if (e < N_EDGES) {
        int d = load_idx(ei, (long long)N_EDGES + e);
        atomicAdd(&g_deg[d], 1);
    }
}

// ---------------- multi-block scan -------------------------------------------
// Safe for any blockDim multiple of 32: ALL lanes of warp 0 execute the
// second-level shuffles (lanes >= nw contribute 0).
__device__ __forceinline__ int block_incl_scan(int v, int* warp_sums) {
    int tid = threadIdx.x, lane = tid & 31, w = tid >> 5;
    int nw = blockDim.x >> 5;
    int incl = v;
    #pragma unroll
    for (int d = 1; d < 32; d <<= 1) {
        int t = __shfl_up_sync(0xffffffffu, incl, d);
        if (lane >= d) incl += t;
    }
    if (lane == 31) warp_sums[w] = incl;
    __syncthreads();
    if (w == 0) {
        int ws = (lane < nw) ? warp_sums[lane] : 0;
        #pragma unroll
        for (int d = 1; d < 32; d <<= 1) {
            int t = __shfl_up_sync(0xffffffffu, ws, d);
            if (lane >= d) ws += t;
        }
        if (lane < nw) warp_sums[lane] = ws;
    }
    __syncthreads();
    return incl + (w > 0 ? warp_sums[w - 1] : 0);
}

// phase A: per-block local inclusive scan of degrees
__global__ void __launch_bounds__(SCAN_B) scanA_kernel() {
    __shared__ int warp_sums[32];
    int i = blockIdx.x * SCAN_B + threadIdx.x;
    int v = (i < N_NODES) ? g_deg[i] : 0;
    int incl = block_incl_scan(v, warp_sums);
    if (i < N_NODES) g_rowstart[i + 1] = incl;   // local inclusive, offset later
    if (threadIdx.x == SCAN_B - 1) g_bsum[blockIdx.x] = incl;
}

// phase B: one block scans the NB block sums (exclusive offsets)
__global__ void __launch_bounds__(128) scanB_kernel() {
    __shared__ int warp_sums[32];
    int t = threadIdx.x;
    int v = (t < NB) ? g_bsum[t] : 0;
    int incl = block_incl_scan(v, warp_sums);
    if (t < NB) g_boff[t] = incl - v;            // exclusive offset per block
    if (t == 0) g_rowstart[0] = 0;
}

// phase C: apply block offsets, derive fill positions
__global__ void __launch_bounds__(SCAN_B) scanC_kernel() {
    int i = blockIdx.x * SCAN_B + threadIdx.x;
    if (i < N_NODES) {
        int incl = g_rowstart[i + 1] + g_boff[blockIdx.x];
        g_rowstart[i + 1] = incl;
        g_fill[i] = incl - g_deg[i];             // exclusive position
    }
}

// ---------------- fill CSR (counting sort of src by dst) ---------------------
__global__ void fill_kernel(const void* __restrict__ ei) {
    int e = blockIdx.x * blockDim.x + threadIdx.x;
    if (e < N_EDGES) {
        int s = load_idx(ei, e);
        int d = load_idx(ei, (long long)N_EDGES + e);
        int pos = atomicAdd(&g_fill[d], 1);
        g_src_sorted[pos] = s;
    }
}

// ---------------- segment mean: one warp per destination node ----------------
__global__ void __launch_bounds__(256) segmean_kernel(const float* __restrict__ feat,
                                                      float* __restrict__ outm) {
    int warp = (blockIdx.x * blockDim.x + threadIdx.x) >> 5;
    if (warp >= N_NODES) return;
    int lane = threadIdx.x & 31;
    int beg = g_rowstart[warp];
    int end = g_rowstart[warp + 1];
    float a0 = 0.f, a1 = 0.f, b0 = 0.f, b1 = 0.f;
    int i = beg;
    for (; i + 1 < end; i += 2) {
        int s0 = g_src_sorted[i];
        int s1 = g_src_sorted[i + 1];
        const float* p0 = feat + (long long)s0 * CH;
        const float* p1 = feat + (long long)s1 * CH;
        a0 += p0[lane]; a1 += p0[lane + 32];
        b0 += p1[lane]; b1 += p1[lane + 32];
    }
    if (i < end) {
        int s0 = g_src_sorted[i];
        const float* p0 = feat + (long long)s0 * CH;
        a0 += p0[lane]; a1 += p0[lane + 32];
    }
    a0 += b0; a1 += b1;
    int cnt = end - beg;
    float inv = 1.0f / (float)max(cnt, 1);
    outm[(long long)warp * CH + lane]      = a0 * inv;
    outm[(long long)warp * CH + lane + 32] = a1 * inv;
}

// ---------------- dense: out = relu?(mean@Wl + b + root@Wr) ------------------
#define DN 32
__global__ void __launch_bounds__(256) dense_kernel(
    const float* __restrict__ mean, const float* __restrict__ root,
    const float* __restrict__ Wl, const float* __restrict__ Wr,
    const float* __restrict__ bias, float* __restrict__ out, int do_relu) {
    __shared__ float  sWl[64 * 64];
    __shared__ float  sWr[64 * 64];
    __shared__ float4 sM[DN * 16];
    __shared__ float4 sR[DN * 16];
    int tid = threadIdx.x;
    int j = tid & 63, g = tid >> 6;        // g in 0..3
    int nodeBase = blockIdx.x * DN;

    for (int i = tid; i < 64 * 16; i += 256) {
        ((float4*)sWl)[i] = ((const float4*)Wl)[i];
        ((float4*)sWr)[i] = ((const float4*)Wr)[i];
    }
    for (int i = tid; i < DN * 16; i += 256) {
        int node = nodeBase + (i >> 4);
        int c = i & 15;
        float4 z = make_float4(0.f, 0.f, 0.f, 0.f);
        sM[i] = (node < N_NODES) ? ((const float4*)mean)[(long long)node * 16 + c] : z;
        sR[i] = (node < N_NODES) ? ((const float4*)root)[(long long)node * 16 + c] : z;
    }
    __syncthreads();

    float bj = bias[j];
    float acc[8];
    #pragma unroll
    for (int i = 0; i < 8; ++i) acc[i] = bj;

    #pragma unroll 4
    for (int k4 = 0; k4 < 16; ++k4) {
        float wl0 = sWl[(k4 * 4 + 0) * 64 + j];
        float wl1 = sWl[(k4 * 4 + 1) * 64 + j];
        float wl2 = sWl[(k4 * 4 + 2) * 64 + j];
        float wl3 = sWl[(k4 * 4 + 3) * 64 + j];
        float wr0 = sWr[(k4 * 4 + 0) * 64 + j];
        float wr1 = sWr[(k4 * 4 + 1) * 64 + j];
        float wr2 = sWr[(k4 * 4 + 2) * 64 + j];
        float wr3 = sWr[(k4 * 4 + 3) * 64 + j];
        #pragma unroll
        for (int i = 0; i < 8; ++i) {
            int ln = g * 8 + i;
            float4 m = sM[ln * 16 + k4];
            float4 r = sR[ln * 16 + k4];
            float a = acc[i];
            a = fmaf(m.x, wl0, a); a = fmaf(m.y, wl1, a);
            a = fmaf(m.z, wl2, a); a = fmaf(m.w, wl3, a);
            a = fmaf(r.x, wr0, a); a = fmaf(r.y, wr1, a);
            a = fmaf(r.z, wr2, a); a = fmaf(r.w, wr3, a);
            acc[i] = a;
        }
    }

    #pragma unroll
    for (int i = 0; i < 8; ++i) {
        int node = nodeBase + g * 8 + i;
        if (node < N_NODES) {
            float v = acc[i];
            if (do_relu) v = fmaxf(v, 0.f);
            out[(long long)node * CH + j] = v;
        }
    }
}

// ---------------- fc head: pred[n] = h2[n,:] @ Wfc + bfc ---------------------
__global__ void __launch_bounds__(256) fc_kernel(const float* __restrict__ h,
                                                 const float* __restrict__ Wfc,
                                                 const float* __restrict__ bfc,
                                                 float* __restrict__ out) {
    int warp = (blockIdx.x * blockDim.x + threadIdx.x) >> 5;
    if (warp >= N_NODES) return;
    int lane = threadIdx.x & 31;
    const float* p = h + (long long)warp * CH;
    float v = p[lane] * Wfc[lane] + p[lane + 32] * Wfc[lane + 32];
    #pragma unroll
    for (int d = 16; d; d >>= 1) v += __shfl_xor_sync(0xffffffffu, v, d);
    if (lane == 0) out[warp] = v + bfc[0];
}

// ---------------- launch -----------------------------------------------------
extern "C" void kernel_launch(void* const* d_in, const int* in_sizes, int n_in,
                              void* d_out, int out_size) {
    const float* x   = (const float*)d_in[0];
    const void*  ei  = d_in[1];
    const float* W1l = (const float*)d_in[2];
    const float* b1  = (const float*)d_in[3];
    const float* W1r = (const float*)d_in[4];
    const float* W2l = (const float*)d_in[5];
    const float* b2  = (const float*)d_in[6];
    const float* W2r = (const float*)d_in[7];
    const float* Wfc = (const float*)d_in[8];
    const float* bfc = (const float*)d_in[9];
    float* out = (float*)d_out;

    float *xin, *mean, *h1, *h2;
    cudaGetSymbolAddress((void**)&xin,  g_xin);
    cudaGetSymbolAddress((void**)&mean, g_mean);
    cudaGetSymbolAddress((void**)&h1,   g_h1);
    cudaGetSymbolAddress((void**)&h2,   g_h2);

    const int T = 256;
    int gridPrep  = (N_NODES * CH / 4 + T - 1) / T;
    int gridEdge  = (N_EDGES + T - 1) / T;
    int gridWarp  = (N_NODES * 32 + T - 1) / T;   // one warp per node
    int gridDense = (N_NODES + DN - 1) / DN;

    detect_kernel<<<1, 1>>>(ei);
    prep_kernel<<<gridPrep, T>>>(x);
    count_kernel<<<gridEdge, T>>>(ei);
    scanA_kernel<<<NB, SCAN_B>>>();
    scanB_kernel<<<1, 128>>>();
    scanC_kernel<<<NB, SCAN_B>>>();
    fill_kernel<<<gridEdge, T>>>(ei);

    // layer 1
    segmean_kernel<<<gridWarp, T>>>(xin, mean);
    dense_kernel<<<gridDense, T>>>(mean, xin, W1l, W1r, b1, h1, 1);
    // layer 2
    segmean_kernel<<<gridWarp, T>>>(h1, mean);
    dense_kernel<<<gridDense, T>>>(mean, h1, W2l, W2r, b2, h2, 1);
    // head
    fc_kernel<<<gridWarp, T>>>(h2, Wfc, bfc, out);
}

// round 4
// speedup vs baseline: 2.3376x; 1.2969x over previous
#include <cuda_runtime.h>
#include <cuda_bf16.h>
#include <math.h>
#include <stdint.h>

#define N_NODES 100000
#define N_EDGES 1200000
#define CH 64
#define SCAN_B 1024
#define NB ((N_NODES + SCAN_B - 1) / SCAN_B)   // 98 blocks

// ---------------- scratch (static device memory; no allocs allowed) ----------
__device__ float g_xin [N_NODES * CH];
__device__ float g_mean[N_NODES * CH];
__device__ float g_h1  [N_NODES * CH];
__device__ float g_h2  [N_NODES * CH];
__device__ int   g_deg [N_NODES];
__device__ int   g_rowstart[N_NODES + 1];
__device__ int   g_fill[N_NODES];
__device__ int   g_src_sorted[N_EDGES];
__device__ int   g_bsum[NB];
__device__ int   g_boff[NB];
__device__ int   g_is64;

// ---------------- edge-index dtype detection (int64 vs int32) ----------------
__global__ void detect_kernel(const void* ei) {
    const int* w = (const int*)ei;
    int ok64 = 1;
    for (int i = 0; i < 64; ++i)
        if (w[2 * i + 1] != 0) ok64 = 0;
    g_is64 = ok64;
}

__device__ __forceinline__ int load_idx(const void* ei, long long pos) {
    if (g_is64) return (int)((const long long*)ei)[pos];
    return ((const int*)ei)[pos];
}

// ---------------- prep: nan_to_num(x) -> xin (float4), zero degrees ----------
__global__ void prep_kernel(const float* __restrict__ x) {
    int i = blockIdx.x * blockDim.x + threadIdx.x;
    if (i < N_NODES * CH / 4) {
        float4 v = ((const float4*)x)[i];
        v.x = isnan(v.x) ? 0.f : v.x;
        v.y = isnan(v.y) ? 0.f : v.y;
        v.z = isnan(v.z) ? 0.f : v.z;
        v.w = isnan(v.w) ? 0.f : v.w;
        ((float4*)g_xin)[i] = v;
    }
    if (i < N_NODES) g_deg[i] = 0;
}

// ---------------- count degrees ----------------------------------------------
__global__ void count_kernel(const void* __restrict__ ei) {
    int e = blockIdx.x * blockDim.x + threadIdx.x;
    if (e < N_EDGES) {
        int d = load_idx(ei, (long long)N_EDGES + e);
        atomicAdd(&g_deg[d], 1);
    }
}

// ---------------- multi-block scan -------------------------------------------
__device__ __forceinline__ int block_incl_scan(int v, int* warp_sums) {
    int tid = threadIdx.x, lane = tid & 31, w = tid >> 5;
    int nw = blockDim.x >> 5;
    int incl = v;
    #pragma unroll
    for (int d = 1; d < 32; d <<= 1) {
        int t = __shfl_up_sync(0xffffffffu, incl, d);
        if (lane >= d) incl += t;
    }
    if (lane == 31) warp_sums[w] = incl;
    __syncthreads();
    if (w == 0) {
        int ws = (lane < nw) ? warp_sums[lane] : 0;
        #pragma unroll
        for (int d = 1; d < 32; d <<= 1) {
            int t = __shfl_up_sync(0xffffffffu, ws, d);
            if (lane >= d) ws += t;
        }
        if (lane < nw) warp_sums[lane] = ws;
    }
    __syncthreads();
    return incl + (w > 0 ? warp_sums[w - 1] : 0);
}

__global__ void __launch_bounds__(SCAN_B) scanA_kernel() {
    __shared__ int warp_sums[32];
    int i = blockIdx.x * SCAN_B + threadIdx.x;
    int v = (i < N_NODES) ? g_deg[i] : 0;
    int incl = block_incl_scan(v, warp_sums);
    if (i < N_NODES) g_rowstart[i + 1] = incl;
    if (threadIdx.x == SCAN_B - 1) g_bsum[blockIdx.x] = incl;
}

__global__ void __launch_bounds__(128) scanB_kernel() {
    __shared__ int warp_sums[32];
    int t = threadIdx.x;
    int v = (t < NB) ? g_bsum[t] : 0;
    int incl = block_incl_scan(v, warp_sums);
    if (t < NB) g_boff[t] = incl - v;
    if (t == 0) g_rowstart[0] = 0;
}

__global__ void __launch_bounds__(SCAN_B) scanC_kernel() {
    int i = blockIdx.x * SCAN_B + threadIdx.x;
    if (i < N_NODES) {
        int incl = g_rowstart[i + 1] + g_boff[blockIdx.x];
        g_rowstart[i + 1] = incl;
        g_fill[i] = incl - g_deg[i];
    }
}

// ---------------- fill CSR (counting sort of src by dst) ---------------------
__global__ void fill_kernel(const void* __restrict__ ei) {
    int e = blockIdx.x * blockDim.x + threadIdx.x;
    if (e < N_EDGES) {
        int s = load_idx(ei, e);
        int d = load_idx(ei, (long long)N_EDGES + e);
        int pos = atomicAdd(&g_fill[d], 1);
        g_src_sorted[pos] = s;
    }
}

// ---------------- segment mean: one warp per destination node ----------------
__global__ void __launch_bounds__(256) segmean_kernel(const float* __restrict__ feat,
                                                      float* __restrict__ outm) {
    int warp = (blockIdx.x * blockDim.x + threadIdx.x) >> 5;
    if (warp >= N_NODES) return;
    int lane = threadIdx.x & 31;
    int beg = g_rowstart[warp];
    int end = g_rowstart[warp + 1];
    float a0 = 0.f, a1 = 0.f, b0 = 0.f, b1 = 0.f;
    int i = beg;
    for (; i + 1 < end; i += 2) {
        int s0 = g_src_sorted[i];
        int s1 = g_src_sorted[i + 1];
        const float* p0 = feat + (long long)s0 * CH;
        const float* p1 = feat + (long long)s1 * CH;
        a0 += p0[lane]; a1 += p0[lane + 32];
        b0 += p1[lane]; b1 += p1[lane + 32];
    }
    if (i < end) {
        int s0 = g_src_sorted[i];
        const float* p0 = feat + (long long)s0 * CH;
        a0 += p0[lane]; a1 += p0[lane + 32];
    }
    a0 += b0; a1 += b1;
    int cnt = end - beg;
    float inv = 1.0f / (float)max(cnt, 1);
    outm[(long long)warp * CH + lane]      = a0 * inv;
    outm[(long long)warp * CH + lane + 32] = a1 * inv;
}

// ---------------- dense via split-bf16 mma.sync ------------------------------
// out[128-tile, 64] = relu( [mean|root] @ [Wl;Wr] + b )
// Each fp32 value split into bf16 hi + bf16 lo; 3 MMAs per tile recover
// ~1e-5 accuracy: Ahi*Bhi + Ahi*Blo + Alo*Bhi  (lo*lo dropped).
#define SA_STRIDE 72     // bf16 elems per A row (64 used + pad) -> 36 words
#define SB_STRIDE 136    // bf16 elems per B^T row (128 used + pad) -> 68 words
#define SA_ELEMS (128 * SA_STRIDE)
#define SB_ELEMS (64 * SB_STRIDE)
#define DENSE_SMEM ((2 * SA_ELEMS + 2 * SB_ELEMS) * 2)   // bytes = 71680

__device__ __forceinline__ void mma16816(float* c, const uint32_t* a, const uint32_t* b) {
    asm volatile(
        "mma.sync.aligned.m16n8k16.row.col.f32.bf16.bf16.f32 "
        "{%0,%1,%2,%3}, {%4,%5,%6,%7}, {%8,%9}, {%0,%1,%2,%3};"
        : "+f"(c[0]), "+f"(c[1]), "+f"(c[2]), "+f"(c[3])
        : "r"(a[0]), "r"(a[1]), "r"(a[2]), "r"(a[3]), "r"(b[0]), "r"(b[1]));
}

__device__ __forceinline__ void split_bf16(float v, __nv_bfloat16& hi, __nv_bfloat16& lo) {
    hi = __float2bfloat16_rn(v);
    lo = __float2bfloat16_rn(v - __bfloat162float(hi));
}

__global__ void __launch_bounds__(128) dense_mma_kernel(
    const float* __restrict__ mean, const float* __restrict__ root,
    const float* __restrict__ Wl, const float* __restrict__ Wr,
    const float* __restrict__ bias, float* __restrict__ out) {
    extern __shared__ __nv_bfloat16 smem[];
    __nv_bfloat16* sAhi = smem;
    __nv_bfloat16* sAlo = smem + SA_ELEMS;
    __nv_bfloat16* sBhi = smem + 2 * SA_ELEMS;
    __nv_bfloat16* sBlo = smem + 2 * SA_ELEMS + SB_ELEMS;
    uint32_t* uAhi = (uint32_t*)sAhi;
    uint32_t* uAlo = (uint32_t*)sAlo;
    uint32_t* uBhi = (uint32_t*)sBhi;
    uint32_t* uBlo = (uint32_t*)sBlo;

    int tid = threadIdx.x;
    int w = tid >> 5, lane = tid & 31;
    int base = blockIdx.x * 128;

    // ---- stage weights transposed + split: sB[n][k], Wl at k 0..63, Wr 64..127
    for (int idx = tid; idx < 64 * 64; idx += 128) {
        int k = idx >> 6, n = idx & 63;
        __nv_bfloat16 hi, lo;
        split_bf16(Wl[idx], hi, lo);
        sBhi[n * SB_STRIDE + k] = hi;
        sBlo[n * SB_STRIDE + k] = lo;
        split_bf16(Wr[idx], hi, lo);
        sBhi[n * SB_STRIDE + 64 + k] = hi;
        sBlo[n * SB_STRIDE + 64 + k] = lo;
    }

    // ---- bias into acc
    int cgrp = lane & 3;           // column group within n8 tile
    int rIn = lane >> 2;           // row within m16 tile (0..7)
    float acc[2][8][4];
    #pragma unroll
    for (int nt = 0; nt < 8; ++nt) {
        int ch = nt * 8 + 2 * cgrp;
        float bv0 = bias[ch], bv1 = bias[ch + 1];
        #pragma unroll
        for (int mt = 0; mt < 2; ++mt) {
            acc[mt][nt][0] = bv0; acc[mt][nt][1] = bv1;
            acc[mt][nt][2] = bv0; acc[mt][nt][3] = bv1;
        }
    }

    #pragma unroll
    for (int phase = 0; phase < 2; ++phase) {
        // ---- stage A (mean for phase 0, root for phase 1), row per thread
        __syncthreads();   // protect smem from previous phase's readers
        {
            const float* feat = phase == 0 ? mean : root;
            int node = base + tid;
            bool valid = node < N_NODES;
            const float4* src = (const float4*)(feat + (long long)node * CH);
            #pragma unroll
            for (int q = 0; q < 16; ++q) {
                float4 v = valid ? src[q]
                                 : make_float4(0.f, 0.f, 0.f, 0.f);
                __nv_bfloat16 h0, l0, h1, l1, h2, l2, h3, l3;
                split_bf16(v.x, h0, l0); split_bf16(v.y, h1, l1);
                split_bf16(v.z, h2, l2); split_bf16(v.w, h3, l3);
                __nv_bfloat162 ph0; ph0.x = h0; ph0.y = h1;
                __nv_bfloat162 ph1; ph1.x = h2; ph1.y = h3;
                __nv_bfloat162 pl0; pl0.x = l0; pl0.y = l1;
                __nv_bfloat162 pl1; pl1.x = l2; pl1.y = l3;
                int wbase = tid * (SA_STRIDE / 2) + q * 2;
                uAhi[wbase]     = *(uint32_t*)&ph0;
                uAhi[wbase + 1] = *(uint32_t*)&ph1;
                uAlo[wbase]     = *(uint32_t*)&pl0;
                uAlo[wbase + 1] = *(uint32_t*)&pl1;
            }
        }
        __syncthreads();

        // ---- mma main loop: K=64 in 4 k16 steps
        #pragma unroll
        for (int s = 0; s < 4; ++s) {
            uint32_t ah[2][4], al[2][4];
            #pragma unroll
            for (int mt = 0; mt < 2; ++mt) {
                int row = w * 32 + mt * 16 + rIn;
                int wb = row * (SA_STRIDE / 2) + s * 8 + cgrp;
                ah[mt][0] = uAhi[wb];
                ah[mt][1] = uAhi[wb + 8 * (SA_STRIDE / 2)];
                ah[mt][2] = uAhi[wb + 4];
                ah[mt][3] = uAhi[wb + 8 * (SA_STRIDE / 2) + 4];
                al[mt][0] = uAlo[wb];
                al[mt][1] = uAlo[wb + 8 * (SA_STRIDE / 2)];
                al[mt][2] = uAlo[wb + 4];
                al[mt][3] = uAlo[wb + 8 * (SA_STRIDE / 2) + 4];
            }
            #pragma unroll
            for (int nt = 0; nt < 8; ++nt) {
                int n = nt * 8 + (lane >> 2);
                int bw = n * (SB_STRIDE / 2) + phase * 32 + s * 8 + cgrp;
                uint32_t bh[2] = { uBhi[bw], uBhi[bw + 4] };
                uint32_t bl[2] = { uBlo[bw], uBlo[bw + 4] };
                #pragma unroll
                for (int mt = 0; mt < 2; ++mt) {
                    mma16816(acc[mt][nt], ah[mt], bh);
                    mma16816(acc[mt][nt], ah[mt], bl);
                    mma16816(acc[mt][nt], al[mt], bh);
                }
            }
        }
    }

    // ---- epilogue: relu + store
    #pragma unroll
    for (int mt = 0; mt < 2; ++mt) {
        int r0 = base + w * 32 + mt * 16 + rIn;
        int r1 = r0 + 8;
        #pragma unroll
        for (int nt = 0; nt < 8; ++nt) {
            int ch = nt * 8 + 2 * cgrp;
            if (r0 < N_NODES) {
                float2 v = make_float2(fmaxf(acc[mt][nt][0], 0.f),
                                       fmaxf(acc[mt][nt][1], 0.f));
                *(float2*)(out + (long long)r0 * CH + ch) = v;
            }
            if (r1 < N_NODES) {
                float2 v = make_float2(fmaxf(acc[mt][nt][2], 0.f),
                                       fmaxf(acc[mt][nt][3], 0.f));
                *(float2*)(out + (long long)r1 * CH + ch) = v;
            }
        }
    }
}

// ---------------- fc head: pred[n] = h2[n,:] @ Wfc + bfc ---------------------
__global__ void __launch_bounds__(256) fc_kernel(const float* __restrict__ h,
                                                 const float* __restrict__ Wfc,
                                                 const float* __restrict__ bfc,
                                                 float* __restrict__ out) {
    int warp = (blockIdx.x * blockDim.x + threadIdx.x) >> 5;
    if (warp >= N_NODES) return;
    int lane = threadIdx.x & 31;
    const float* p = h + (long long)warp * CH;
    float v = p[lane] * Wfc[lane] + p[lane + 32] * Wfc[lane + 32];
    #pragma unroll
    for (int d = 16; d; d >>= 1) v += __shfl_xor_sync(0xffffffffu, v, d);
    if (lane == 0) out[warp] = v + bfc[0];
}

// ---------------- launch -----------------------------------------------------
extern "C" void kernel_launch(void* const* d_in, const int* in_sizes, int n_in,
                              void* d_out, int out_size) {
    const float* x   = (const float*)d_in[0];
    const void*  ei  = d_in[1];
    const float* W1l = (const float*)d_in[2];
    const float* b1  = (const float*)d_in[3];
    const float* W1r = (const float*)d_in[4];
    const float* W2l = (const float*)d_in[5];
    const float* b2  = (const float*)d_in[6];
    const float* W2r = (const float*)d_in[7];
    const float* Wfc = (const float*)d_in[8];
    const float* bfc = (const float*)d_in[9];
    float* out = (float*)d_out;

    float *xin, *mean, *h1, *h2;
    cudaGetSymbolAddress((void**)&xin,  g_xin);
    cudaGetSymbolAddress((void**)&mean, g_mean);
    cudaGetSymbolAddress((void**)&h1,   g_h1);
    cudaGetSymbolAddress((void**)&h2,   g_h2);

    cudaFuncSetAttribute(dense_mma_kernel,
                         cudaFuncAttributeMaxDynamicSharedMemorySize, DENSE_SMEM);

    const int T = 256;
    int gridPrep  = (N_NODES * CH / 4 + T - 1) / T;
    int gridEdge  = (N_EDGES + T - 1) / T;
    int gridWarp  = (N_NODES * 32 + T - 1) / T;   // one warp per node
    int gridDense = (N_NODES + 127) / 128;

    detect_kernel<<<1, 1>>>(ei);
    prep_kernel<<<gridPrep, T>>>(x);
    count_kernel<<<gridEdge, T>>>(ei);
    scanA_kernel<<<NB, SCAN_B>>>();
    scanB_kernel<<<1, 128>>>();
    scanC_kernel<<<NB, SCAN_B>>>();
    fill_kernel<<<gridEdge, T>>>(ei);

    // layer 1
    segmean_kernel<<<gridWarp, T>>>(xin, mean);
    dense_mma_kernel<<<gridDense, 128, DENSE_SMEM>>>(mean, xin, W1l, W1r, b1, h1);
    // layer 2
    segmean_kernel<<<gridWarp, T>>>(h1, mean);
    dense_mma_kernel<<<gridDense, 128, DENSE_SMEM>>>(mean, h1, W2l, W2r, b2, h2);
    // head
    fc_kernel<<<gridWarp, T>>>(h2, Wfc, bfc, out);
}

// round 5
// speedup vs baseline: 2.3886x; 1.0218x over previous
#include <cuda_runtime.h>
#include <cuda_bf16.h>
#include <math.h>
#include <stdint.h>

#define N_NODES 100000
#define N_EDGES 1200000
#define CH 64
#define SCAN_B 1024
#define NB ((N_NODES + SCAN_B - 1) / SCAN_B)   // 98 blocks

// ---------------- scratch (static device memory; no allocs allowed) ----------
__device__ float g_xin [N_NODES * CH];
__device__ float g_h1  [N_NODES * CH];
__device__ int   g_deg [N_NODES];
__device__ int   g_rowstart[N_NODES + 1];
__device__ int   g_fill[N_NODES];
__device__ int   g_src_sorted[N_EDGES];
__device__ int   g_bsum[NB];
__device__ int   g_boff[NB];
__device__ int   g_is64;

// ---------------- init: detect edge dtype + zero degrees ---------------------
__global__ void init_kernel(const void* ei) {
    int i = blockIdx.x * blockDim.x + threadIdx.x;
    if (i == 0) {
        const int* w = (const int*)ei;
        int ok64 = 1;
        for (int q = 0; q < 64; ++q)
            if (w[2 * q + 1] != 0) ok64 = 0;
        g_is64 = ok64;
    }
    if (i < N_NODES) g_deg[i] = 0;
}

__device__ __forceinline__ int load_idx(const void* ei, long long pos) {
    if (g_is64) return (int)((const long long*)ei)[pos];
    return ((const int*)ei)[pos];
}

// ---------------- prep (nan_to_num -> xin, float4) + count degrees -----------
__global__ void prepcount_kernel(const float* __restrict__ x,
                                 const void* __restrict__ ei) {
    int i = blockIdx.x * blockDim.x + threadIdx.x;
    if (i < N_NODES * CH / 4) {
        float4 v = ((const float4*)x)[i];
        v.x = isnan(v.x) ? 0.f : v.x;
        v.y = isnan(v.y) ? 0.f : v.y;
        v.z = isnan(v.z) ? 0.f : v.z;
        v.w = isnan(v.w) ? 0.f : v.w;
        ((float4*)g_xin)[i] = v;
    }
    if (i < N_EDGES) {
        int d = load_idx(ei, (long long)N_EDGES + i);
        atomicAdd(&g_deg[d], 1);
    }
}

// ---------------- multi-block scan -------------------------------------------
__device__ __forceinline__ int block_incl_scan(int v, int* warp_sums) {
    int tid = threadIdx.x, lane = tid & 31, w = tid >> 5;
    int nw = blockDim.x >> 5;
    int incl = v;
    #pragma unroll
    for (int d = 1; d < 32; d <<= 1) {
        int t = __shfl_up_sync(0xffffffffu, incl, d);
        if (lane >= d) incl += t;
    }
    if (lane == 31) warp_sums[w] = incl;
    __syncthreads();
    if (w == 0) {
        int ws = (lane < nw) ? warp_sums[lane] : 0;
        #pragma unroll
        for (int d = 1; d < 32; d <<= 1) {
            int t = __shfl_up_sync(0xffffffffu, ws, d);
            if (lane >= d) ws += t;
        }
        if (lane < nw) warp_sums[lane] = ws;
    }
    __syncthreads();
    return incl + (w > 0 ? warp_sums[w - 1] : 0);
}

__global__ void __launch_bounds__(SCAN_B) scanA_kernel() {
    __shared__ int warp_sums[32];
    int i = blockIdx.x * SCAN_B + threadIdx.x;
    int v = (i < N_NODES) ? g_deg[i] : 0;
    int incl = block_incl_scan(v, warp_sums);
    if (i < N_NODES) g_rowstart[i + 1] = incl;
    if (threadIdx.x == SCAN_B - 1) g_bsum[blockIdx.x] = incl;
}

__global__ void __launch_bounds__(128) scanB_kernel() {
    __shared__ int warp_sums[32];
    int t = threadIdx.x;
    int v = (t < NB) ? g_bsum[t] : 0;
    int incl = block_incl_scan(v, warp_sums);
    if (t < NB) g_boff[t] = incl - v;
    if (t == 0) g_rowstart[0] = 0;
}

__global__ void __launch_bounds__(SCAN_B) scanC_kernel() {
    int i = blockIdx.x * SCAN_B + threadIdx.x;
    if (i < N_NODES) {
        int incl = g_rowstart[i + 1] + g_boff[blockIdx.x];
        g_rowstart[i + 1] = incl;
        g_fill[i] = incl - g_deg[i];
    }
}

// ---------------- fill CSR (counting sort of src by dst) ---------------------
__global__ void fill_kernel(const void* __restrict__ ei) {
    int e = blockIdx.x * blockDim.x + threadIdx.x;
    if (e < N_EDGES) {
        int s = load_idx(ei, e);
        int d = load_idx(ei, (long long)N_EDGES + e);
        int pos = atomicAdd(&g_fill[d], 1);
        g_src_sorted[pos] = s;
    }
}

// ---------------- fused: segment-mean + split-bf16 MMA dense (+optional fc) --
// Per block: 128 nodes, 256 threads (8 warps, one m16 row-tile per warp).
// Phase 0: warps gather CSR rows, compute mean, write split-bf16 into sA.
// Phase 1: stage root features (same gfeat) into sA.
// Each phase: 4 k16 steps x 8 n-tiles x 3 compensated MMAs.
#define SA_STRIDE 72     // bf16 per A row (64 used + pad) -> 36 words
#define SB_STRIDE 136    // bf16 per B^T row (128 used + pad) -> 68 words
#define SA_ELEMS (128 * SA_STRIDE)
#define SB_ELEMS (64 * SB_STRIDE)
#define DENSE_SMEM ((2 * SA_ELEMS + 2 * SB_ELEMS) * 2)   // 71680 bytes

__device__ __forceinline__ void mma16816(float* c, const uint32_t* a, const uint32_t* b) {
    asm volatile(
        "mma.sync.aligned.m16n8k16.row.col.f32.bf16.bf16.f32 "
        "{%0,%1,%2,%3}, {%4,%5,%6,%7}, {%8,%9}, {%0,%1,%2,%3};"
        : "+f"(c[0]), "+f"(c[1]), "+f"(c[2]), "+f"(c[3])
        : "r"(a[0]), "r"(a[1]), "r"(a[2]), "r"(a[3]), "r"(b[0]), "r"(b[1]));
}

__device__ __forceinline__ void split_bf16(float v, __nv_bfloat16& hi, __nv_bfloat16& lo) {
    hi = __float2bfloat16_rn(v);
    lo = __float2bfloat16_rn(v - __bfloat162float(hi));
}

__global__ void __launch_bounds__(256) fused_layer_kernel(
    const float* __restrict__ gfeat,          // node features (gather src + root)
    const float* __restrict__ Wl, const float* __restrict__ Wr,
    const float* __restrict__ bias,
    const float* __restrict__ Wfc, const float* __restrict__ bfc,
    float* __restrict__ out, int do_fc) {
    extern __shared__ __nv_bfloat16 smem[];
    __nv_bfloat16* sAhi = smem;
    __nv_bfloat16* sAlo = smem + SA_ELEMS;
    __nv_bfloat16* sBhi = smem + 2 * SA_ELEMS;
    __nv_bfloat16* sBlo = smem + 2 * SA_ELEMS + SB_ELEMS;
    uint32_t* uAhi = (uint32_t*)sAhi;
    uint32_t* uAlo = (uint32_t*)sAlo;
    uint32_t* uBhi = (uint32_t*)sBhi;
    uint32_t* uBlo = (uint32_t*)sBlo;

    int tid = threadIdx.x;
    int w = tid >> 5, lane = tid & 31;
    int base = blockIdx.x * 128;
    int cgrp = lane & 3;           // quad column group
    int rIn = lane >> 2;           // row within m16 tile (0..7)

    // ---- stage weights transposed + split: sB[n][k], Wl k 0..63, Wr k 64..127
    for (int idx = tid; idx < 64 * 64; idx += 256) {
        int k = idx >> 6, n = idx & 63;
        __nv_bfloat16 hi, lo;
        split_bf16(Wl[idx], hi, lo);
        sBhi[n * SB_STRIDE + k] = hi;
        sBlo[n * SB_STRIDE + k] = lo;
        split_bf16(Wr[idx], hi, lo);
        sBhi[n * SB_STRIDE + 64 + k] = hi;
        sBlo[n * SB_STRIDE + 64 + k] = lo;
    }

    // ---- phase 0 staging: gather + mean, split-bf16 straight into sA -------
    // warp w handles rows w*16 .. w*16+15; lane owns channel pair 2*lane,2*lane+1
    {
        int row0 = w * 16;
        for (int i = 0; i < 16; ++i) {
            int node = base + row0 + i;
            float ax = 0.f, ay = 0.f, bx = 0.f, by = 0.f;
            if (node < N_NODES) {
                int beg = g_rowstart[node];
                int end = g_rowstart[node + 1];
                int e = beg;
                for (; e + 1 < end; e += 2) {
                    int s0 = g_src_sorted[e];
                    int s1 = g_src_sorted[e + 1];
                    float2 v0 = ((const float2*)(gfeat + (long long)s0 * CH))[lane];
                    float2 v1 = ((const float2*)(gfeat + (long long)s1 * CH))[lane];
                    ax += v0.x; ay += v0.y;
                    bx += v1.x; by += v1.y;
                }
                if (e < end) {
                    int s0 = g_src_sorted[e];
                    float2 v0 = ((const float2*)(gfeat + (long long)s0 * CH))[lane];
                    ax += v0.x; ay += v0.y;
                }
                ax += bx; ay += by;
                float inv = 1.0f / (float)max(end - beg, 1);
                ax *= inv; ay *= inv;
            }
            __nv_bfloat16 h0, l0, h1, l1;
            split_bf16(ax, h0, l0); split_bf16(ay, h1, l1);
            __nv_bfloat162 ph; ph.x = h0; ph.y = h1;
            __nv_bfloat162 pl; pl.x = l0; pl.y = l1;
            uAhi[(row0 + i) * (SA_STRIDE / 2) + lane] = *(uint32_t*)&ph;
            uAlo[(row0 + i) * (SA_STRIDE / 2) + lane] = *(uint32_t*)&pl;
        }
    }

    // ---- bias into acc ------------------------------------------------------
    float acc[8][4];
    #pragma unroll
    for (int nt = 0; nt < 8; ++nt) {
        int ch = nt * 8 + 2 * cgrp;
        float bv0 = bias[ch], bv1 = bias[ch + 1];
        acc[nt][0] = bv0; acc[nt][1] = bv1;
        acc[nt][2] = bv0; acc[nt][3] = bv1;
    }

    __syncthreads();

    #pragma unroll
    for (int phase = 0; phase < 2; ++phase) {
        if (phase == 1) {
            __syncthreads();   // phase-0 readers done before overwrite
            // stage root features: thread t -> row t>>1, half t&1 (8 float4)
            int row = tid >> 1, half = tid & 1;
            int node = base + row;
            bool valid = node < N_NODES;
            const float4* src = (const float4*)(gfeat + (long long)node * CH) + half * 8;
            int wbase = row * (SA_STRIDE / 2) + half * 16;
            #pragma unroll
            for (int q = 0; q < 8; ++q) {
                float4 v = valid ? src[q] : make_float4(0.f, 0.f, 0.f, 0.f);
                __nv_bfloat16 h0, l0, h1, l1, h2, l2, h3, l3;
                split_bf16(v.x, h0, l0); split_bf16(v.y, h1, l1);
                split_bf16(v.z, h2, l2); split_bf16(v.w, h3, l3);
                __nv_bfloat162 ph0; ph0.x = h0; ph0.y = h1;
                __nv_bfloat162 ph1; ph1.x = h2; ph1.y = h3;
                __nv_bfloat162 pl0; pl0.x = l0; pl0.y = l1;
                __nv_bfloat162 pl1; pl1.x = l2; pl1.y = l3;
                uAhi[wbase + q * 2]     = *(uint32_t*)&ph0;
                uAhi[wbase + q * 2 + 1] = *(uint32_t*)&ph1;
                uAlo[wbase + q * 2]     = *(uint32_t*)&pl0;
                uAlo[wbase + q * 2 + 1] = *(uint32_t*)&pl1;
            }
            __syncthreads();
        }

        // ---- mma main loop: K=64 in 4 k16 steps
        #pragma unroll
        for (int s = 0; s < 4; ++s) {
            uint32_t ah[4], al[4];
            int row = w * 16 + rIn;
            int wb = row * (SA_STRIDE / 2) + s * 8 + cgrp;
            const int R8 = 8 * (SA_STRIDE / 2);
            ah[0] = uAhi[wb];       ah[1] = uAhi[wb + R8];
            ah[2] = uAhi[wb + 4];   ah[3] = uAhi[wb + R8 + 4];
            al[0] = uAlo[wb];       al[1] = uAlo[wb + R8];
            al[2] = uAlo[wb + 4];   al[3] = uAlo[wb + R8 + 4];
            #pragma unroll
            for (int nt = 0; nt < 8; ++nt) {
                int n = nt * 8 + (lane >> 2);
                int bw = n * (SB_STRIDE / 2) + phase * 32 + s * 8 + cgrp;
                uint32_t bh[2] = { uBhi[bw], uBhi[bw + 4] };
                uint32_t bl[2] = { uBlo[bw], uBlo[bw + 4] };
                mma16816(acc[nt], ah, bh);
                mma16816(acc[nt], ah, bl);
                mma16816(acc[nt], al, bh);
            }
        }
    }

    // ---- epilogue -----------------------------------------------------------
    int r0 = base + w * 16 + rIn;
    int r1 = r0 + 8;
    if (do_fc) {
        // pred[r] = sum_ch relu(h[r][ch]) * Wfc[ch] + bfc
        float p0 = 0.f, p1 = 0.f;
        #pragma unroll
        for (int nt = 0; nt < 8; ++nt) {
            int ch = nt * 8 + 2 * cgrp;
            float w0 = Wfc[ch], w1 = Wfc[ch + 1];
            p0 += fmaxf(acc[nt][0], 0.f) * w0 + fmaxf(acc[nt][1], 0.f) * w1;
            p1 += fmaxf(acc[nt][2], 0.f) * w0 + fmaxf(acc[nt][3], 0.f) * w1;
        }
        p0 += __shfl_xor_sync(0xffffffffu, p0, 1);
        p0 += __shfl_xor_sync(0xffffffffu, p0, 2);
        p1 += __shfl_xor_sync(0xffffffffu, p1, 1);
        p1 += __shfl_xor_sync(0xffffffffu, p1, 2);
        if (cgrp == 0) {
            float bv = bfc[0];
            if (r0 < N_NODES) out[r0] = p0 + bv;
            if (r1 < N_NODES) out[r1] = p1 + bv;
        }
    } else {
        #pragma unroll
        for (int nt = 0; nt < 8; ++nt) {
            int ch = nt * 8 + 2 * cgrp;
            if (r0 < N_NODES) {
                float2 v = make_float2(fmaxf(acc[nt][0], 0.f),
                                       fmaxf(acc[nt][1], 0.f));
                *(float2*)(out + (long long)r0 * CH + ch) = v;
            }
            if (r1 < N_NODES) {
                float2 v = make_float2(fmaxf(acc[nt][2], 0.f),
                                       fmaxf(acc[nt][3], 0.f));
                *(float2*)(out + (long long)r1 * CH + ch) = v;
            }
        }
    }
}

// ---------------- launch -----------------------------------------------------
extern "C" void kernel_launch(void* const* d_in, const int* in_sizes, int n_in,
                              void* d_out, int out_size) {
    const float* x   = (const float*)d_in[0];
    const void*  ei  = d_in[1];
    const float* W1l = (const float*)d_in[2];
    const float* b1  = (const float*)d_in[3];
    const float* W1r = (const float*)d_in[4];
    const float* W2l = (const float*)d_in[5];
    const float* b2  = (const float*)d_in[6];
    const float* W2r = (const float*)d_in[7];
    const float* Wfc = (const float*)d_in[8];
    const float* bfc = (const float*)d_in[9];
    float* out = (float*)d_out;

    float *xin, *h1;
    cudaGetSymbolAddress((void**)&xin, g_xin);
    cudaGetSymbolAddress((void**)&h1,  g_h1);

    cudaFuncSetAttribute(fused_layer_kernel,
                         cudaFuncAttributeMaxDynamicSharedMemorySize, DENSE_SMEM);

    const int T = 256;
    int gridInit = (N_NODES + T - 1) / T;
    int gridPC   = (N_NODES * CH / 4 + T - 1) / T;   // covers prep(1.6M) & count(1.2M)
    int gridEdge = (N_EDGES + T - 1) / T;
    int gridFuse = (N_NODES + 127) / 128;

    init_kernel<<<gridInit, T>>>(ei);
    prepcount_kernel<<<gridPC, T>>>(x, ei);
    scanA_kernel<<<NB, SCAN_B>>>();
    scanB_kernel<<<1, 128>>>();
    scanC_kernel<<<NB, SCAN_B>>>();
    fill_kernel<<<gridEdge, T>>>(ei);

    // layer 1: gather(mean of xin) + dense -> h1
    fused_layer_kernel<<<gridFuse, 256, DENSE_SMEM>>>(xin, W1l, W1r, b1,
                                                      Wfc, bfc, h1, 0);
    // layer 2 + fc head: gather(mean of h1) + dense + fc -> out
    fused_layer_kernel<<<gridFuse, 256, DENSE_SMEM>>>(h1, W2l, W2r, b2,
                                                      Wfc, bfc, out, 1);
}